// round 10
// baseline (speedup 1.0000x reference)
#include <cuda_runtime.h>
#include <cuda_bf16.h>
#include <cstdint>

// Problem constants (fixed by the dataset)
#define BB 32      // batch
#define LL 128     // sequence length
#define TT 63      // tree nodes (2^6 - 1)
#define EE 128     // embedding dim
#define CC 128     // conv/encoder channels
#define HH 256     // GRU hidden
#define GG 768     // 3*H gate columns
#define VV 50000   // vocab

// ---------------------------------------------------------------------------
// f32x2 helpers
// ---------------------------------------------------------------------------
__device__ __forceinline__ unsigned long long fma2(unsigned long long a,
                                                   unsigned long long b,
                                                   unsigned long long c) {
    unsigned long long d;
    asm("fma.rn.f32x2 %0, %1, %2, %3;" : "=l"(d) : "l"(a), "l"(b), "l"(c));
    return d;
}
__device__ __forceinline__ unsigned long long pk2(float v) {
    unsigned long long r;
    asm("mov.b64 %0, {%1, %1};" : "=l"(r) : "f"(v));
    return r;
}
__device__ __forceinline__ float2 upk(unsigned long long v) {
    float2 f;
    asm("mov.b64 {%0, %1}, %2;" : "=f"(f.x), "=f"(f.y) : "l"(v));
    return f;
}
__device__ __forceinline__ uint32_t smem_u32(const void* p) {
    uint32_t a;
    asm("{ .reg .u64 t; cvta.to.shared.u64 t, %1; cvt.u32.u64 %0, t; }"
        : "=r"(a) : "l"(p));
    return a;
}

// ---------------------------------------------------------------------------
// Device scratch (static only)
// ---------------------------------------------------------------------------
__device__ float d_WcT[EE * CC];            // [k][c]
__device__ float d_WihT0[CC * GG];          // [k][g]
__device__ float d_WihT1[CC * GG];
__device__ float d_P[(long)VV * CC];        // projected vocab: P[v][c]
__device__ float d_enc[BB * LL * CC];
__device__ float d_gi0[(long)BB * LL * GG];
__device__ float d_gi1[(long)BB * LL * GG];

// ---------------------------------------------------------------------------
// Setup: coalesced tiled transposes (32x33 smem tiles, both sides coalesced).
// Grid: 208 blocks = 96 (Wih_f) + 96 (Wih_b) + 16 (Wc). 256 threads.
// ---------------------------------------------------------------------------
__global__ void __launch_bounds__(256) k_setup(const float* __restrict__ Wc,
                                               const float* __restrict__ Wih_f,
                                               const float* __restrict__ Wih_b)
{
    __shared__ float t[32][33];
    const int bid = blockIdx.x;
    const int tid = threadIdx.x;
    const int r = tid >> 5;    // warp -> rows r, r+8, r+16, r+24
    const int j = tid & 31;

    if (bid < 192) {
        const int d = (bid >= 96) ? 1 : 0;
        const float* W  = d ? Wih_b : Wih_f;
        float*       WT = d ? d_WihT1 : d_WihT0;
        const int tb = bid - d * 96;
        const int g0 = (tb % 24) * 32;
        const int k0 = (tb / 24) * 32;
        #pragma unroll
        for (int rr = r; rr < 32; rr += 8)
            t[rr][j] = W[(g0 + rr) * CC + k0 + j];
        __syncthreads();
        #pragma unroll
        for (int rr = r; rr < 32; rr += 8)
            WT[(k0 + rr) * GG + g0 + j] = t[j][rr];
    } else {
        const int tb = bid - 192;          // 0..15
        const int c0 = (tb & 3) * 32;
        const int e0 = (tb >> 2) * 32;
        #pragma unroll
        for (int rr = r; rr < 32; rr += 8)
            t[rr][j] = Wc[(c0 + rr) * EE + e0 + j];
        __syncthreads();
        #pragma unroll
        for (int rr = r; rr < 32; rr += 8)
            d_WcT[(e0 + rr) * CC + c0 + j] = t[j][rr];
    }
}

// ---------------------------------------------------------------------------
// KV: projected-vocab table  P[v] = Wc @ emb[v]
// ---------------------------------------------------------------------------
#define KV_WS 0
#define KV_ES 16384
#define KV_SMEM_FLOATS 24576

__global__ void __launch_bounds__(256, 2) k_vocab(const float* __restrict__ emb)
{
    extern __shared__ float sm[];
    float* ws = sm + KV_WS;   // WcT [k][c] 128x128
    float* es = sm + KV_ES;   // emb rows [64][128]

    const int m0  = blockIdx.x * 64;
    const int tid = threadIdx.x;

    for (int idx = tid; idx < (128 * 128) / 4; idx += 256)
        ((float4*)ws)[idx] = ((const float4*)d_WcT)[idx];
    for (int idx = tid; idx < (64 * 128) / 4; idx += 256) {
        int i  = idx >> 5;
        int k4 = (idx & 31) << 2;
        float4 v = make_float4(0.f, 0.f, 0.f, 0.f);
        if (m0 + i < VV) v = *(const float4*)&emb[(long)(m0 + i) * EE + k4];
        *(float4*)&es[i * 128 + k4] = v;
    }
    __syncthreads();

    const int w     = tid >> 5;
    const int lane  = tid & 31;
    const int c4    = lane << 2;
    const int ibase = w * 8;

    unsigned long long acc2[8][2];
    #pragma unroll
    for (int n = 0; n < 8; n++) { acc2[n][0] = 0ull; acc2[n][1] = 0ull; }

    #pragma unroll 2
    for (int k = 0; k < EE; k += 4) {
        ulonglong2 wu[4];
        #pragma unroll
        for (int kk = 0; kk < 4; kk++)
            wu[kk] = *(const ulonglong2*)&ws[(k + kk) * 128 + c4];

        #pragma unroll
        for (int g = 0; g < 2; g++) {
            float4 e4[4];
            #pragma unroll
            for (int n = 0; n < 4; n++)
                e4[n] = *(float4*)&es[(ibase + g * 4 + n) * 128 + k];
            #pragma unroll
            for (int kk = 0; kk < 4; kk++) {
                #pragma unroll
                for (int n = 0; n < 4; n++) {
                    float ev = (kk == 0) ? e4[n].x : (kk == 1) ? e4[n].y
                             : (kk == 2) ? e4[n].z : e4[n].w;
                    unsigned long long eb = pk2(ev);
                    acc2[g * 4 + n][0] = fma2(eb, wu[kk].x, acc2[g * 4 + n][0]);
                    acc2[g * 4 + n][1] = fma2(eb, wu[kk].y, acc2[g * 4 + n][1]);
                }
            }
        }
    }

    #pragma unroll
    for (int n = 0; n < 8; n++) {
        const int row = m0 + ibase + n;
        if (row < VV) {
            float2 lo = upk(acc2[n][0]);
            float2 hi = upk(acc2[n][1]);
            float4 r = make_float4(lo.x, lo.y, hi.x, hi.y);
            *(float4*)&d_P[(long)row * CC + c4] = r;
        }
    }
}

// ---------------------------------------------------------------------------
// KT: tree encoder = gather P[tok] + bc, heap accumulate, max, relu.
// ---------------------------------------------------------------------------
#define KT_STG 0
#define KT_BCS 16384
#define KT_TKS 16512
#define KT_SMEM_FLOATS 16672

__global__ void __launch_bounds__(256) k_tree(const int* __restrict__ tokens,
                                              const float* __restrict__ bc)
{
    extern __shared__ float sm[];
    float* stg = sm + KT_STG;
    float* bcs = sm + KT_BCS;
    int*   tks = (int*)(sm + KT_TKS);

    const int bl0 = blockIdx.x * 2;
    const int tid = threadIdx.x;

    if (tid < 2 * TT) tks[tid] = tokens[bl0 * TT + tid];
    if (tid < CC)     bcs[tid] = bc[tid];
    __syncthreads();

    const float4* P4 = (const float4*)d_P;
    for (int ci = tid; ci < 126 * 32; ci += 256) {
        const int tl = ci >> 5;
        const int j  = ci & 31;
        const int g  = (tl >= TT) ? 1 : 0;
        const int t  = tl - g * TT;
        float4 v = __ldg(&P4[(long)tks[tl] * 32 + j]);
        float4 b = *(const float4*)&bcs[j * 4];
        v.x += b.x; v.y += b.y; v.z += b.z; v.w += b.w;
        *(float4*)&stg[(g * 64 + t) * 128 + j * 4] = v;
    }
    __syncthreads();

    {
        const int g = tid >> 7;
        const int c = tid & 127;
        float* S = stg + (g * 64) * 128 + c;
        float mx = -3.0e38f;
        #pragma unroll
        for (int t = TT - 1; t >= 31; t--) mx = fmaxf(mx, S[t * 128]);
        #pragma unroll
        for (int t = 30; t >= 0; t--) {
            float v = S[t * 128] + S[(2 * t + 1) * 128] + S[(2 * t + 2) * 128];
            S[t * 128] = v;
            mx = fmaxf(mx, v);
        }
        d_enc[(bl0 + g) * CC + c] = fmaxf(mx, 0.f);
    }
}

// ---------------------------------------------------------------------------
// K2: gi[d] = enc @ Wih[d]^T + bih[d]
// ---------------------------------------------------------------------------
#define K2_WS 0
#define K2_ES 16384
#define K2_BI 24576
#define K2_SMEM_FLOATS 24704

__global__ void __launch_bounds__(256, 2) k_gi(const float* __restrict__ bih_f,
                                               const float* __restrict__ bih_b)
{
    extern __shared__ float sm[];
    float* ws  = sm + K2_WS;
    float* es  = sm + K2_ES;
    float* bis = sm + K2_BI;

    const int mt = blockIdx.x;
    const int nt = blockIdx.y;
    const int d  = blockIdx.z;
    const int m0 = mt * 64;
    const int g0 = nt * 128;
    const int tid = threadIdx.x;

    const float* WT  = d ? d_WihT1 : d_WihT0;
    const float* bih = d ? bih_b   : bih_f;
    float*       gi  = d ? d_gi1   : d_gi0;

    for (int idx = tid; idx < (128 * 128) / 4; idx += 256) {
        int k  = idx >> 5;
        int j4 = (idx & 31) << 2;
        float4 v = *(const float4*)&WT[k * GG + g0 + j4];
        *(float4*)&ws[k * 128 + j4] = v;
    }
    for (int idx = tid; idx < (64 * 128) / 4; idx += 256) {
        int i  = idx >> 5;
        int k4 = (idx & 31) << 2;
        float4 v = *(const float4*)&d_enc[(m0 + i) * CC + k4];
        *(float4*)&es[i * 128 + k4] = v;
    }
    if (tid < 128) bis[tid] = bih[g0 + tid];
    __syncthreads();

    const int w     = tid >> 5;
    const int lane  = tid & 31;
    const int c4    = lane << 2;
    const int ibase = w * 8;

    unsigned long long acc2[8][2];
    #pragma unroll
    for (int n = 0; n < 8; n++) { acc2[n][0] = 0ull; acc2[n][1] = 0ull; }

    #pragma unroll 2
    for (int k = 0; k < CC; k += 4) {
        ulonglong2 wu[4];
        #pragma unroll
        for (int kk = 0; kk < 4; kk++)
            wu[kk] = *(const ulonglong2*)&ws[(k + kk) * 128 + c4];

        #pragma unroll
        for (int g = 0; g < 2; g++) {
            float4 e4[4];
            #pragma unroll
            for (int n = 0; n < 4; n++)
                e4[n] = *(float4*)&es[(ibase + g * 4 + n) * 128 + k];
            #pragma unroll
            for (int kk = 0; kk < 4; kk++) {
                #pragma unroll
                for (int n = 0; n < 4; n++) {
                    float ev = (kk == 0) ? e4[n].x : (kk == 1) ? e4[n].y
                             : (kk == 2) ? e4[n].z : e4[n].w;
                    unsigned long long eb = pk2(ev);
                    acc2[g * 4 + n][0] = fma2(eb, wu[kk].x, acc2[g * 4 + n][0]);
                    acc2[g * 4 + n][1] = fma2(eb, wu[kk].y, acc2[g * 4 + n][1]);
                }
            }
        }
    }

    float4 bv = *(float4*)&bis[c4];
    #pragma unroll
    for (int n = 0; n < 8; n++) {
        float2 lo = upk(acc2[n][0]);
        float2 hi = upk(acc2[n][1]);
        float4 r;
        r.x = lo.x + bv.x;
        r.y = lo.y + bv.y;
        r.z = hi.x + bv.z;
        r.w = hi.y + bv.w;
        *(float4*)&gi[(long)(m0 + ibase + n) * GG + g0 + c4] = r;
    }
}

// ---------------------------------------------------------------------------
// K3 v6: cluster GRU with split arrive/wait + producer/consumer named barrier
// + fast finalize math. Structure otherwise identical to the proven R5 core.
// Barrier balance: arrive at st=0..126, wait at st=1..127 (127 each).
// Remote h pushes skipped on the last step -> no trailing cluster sync needed.
// ---------------------------------------------------------------------------
__device__ __forceinline__ void st_cluster_f32(uint32_t local_addr, uint32_t rank, float v) {
    asm volatile(
        "{\n\t"
        ".reg .b32 r;\n\t"
        "mapa.shared::cluster.u32 r, %0, %1;\n\t"
        "st.shared::cluster.f32 [r], %2;\n\t"
        "}"
        :: "r"(local_addr), "r"(rank), "f"(v) : "memory");
}

__global__ void __launch_bounds__(384, 1) __cluster_dims__(4, 1, 1)
k_gru(const float* __restrict__ Whh_f, const float* __restrict__ bhh_f,
      const float* __restrict__ Whh_b, const float* __restrict__ bhh_b,
      float* __restrict__ out)
{
    __shared__ float hbuf[2][2][HH];     // [buf][bt][unit]
    __shared__ float part[2][2][192];    // [half][bt][row] partial dots

    const int tid = threadIdx.x;
    uint32_t cr;
    asm("mov.u32 %0, %%cluster_ctarank;" : "=r"(cr));

    const int cid = blockIdx.x >> 2;
    const int d   = cid >> 4;
    const int bp  = cid & 15;
    const int U0  = (int)cr << 6;

    const float* Whh = d ? Whh_b : Whh_f;
    const float* bhh = d ? bhh_b : bhh_f;
    const float* gi  = d ? d_gi1 : d_gi0;

    const int w    = tid >> 5;
    const int lane = tid & 31;
    const int rw   = (w % 6) * 32 + lane;  // 0..191  (gate*64 + u)
    const int half = w / 6;                // 0 or 1

    const int gate = rw >> 6, uu = rw & 63;
    float4 wreg[32];
    {
        const float* wrow = &Whh[(gate * HH + U0 + uu) * HH + half * 128];
        #pragma unroll
        for (int i = 0; i < 32; i++) wreg[i] = *(const float4*)&wrow[i * 4];
    }

    const int u_f   = tid & 63;
    const int bt_f  = tid >> 6;
    const int bglob = bp * 2 + bt_f;
    float br = 0.f, bz = 0.f, bn = 0.f;
    uint32_t haddr0 = 0, haddr1 = 0;
    if (tid < 128) {
        br = bhh[U0 + u_f];
        bz = bhh[HH + U0 + u_f];
        bn = bhh[2 * HH + U0 + u_f];
        haddr0 = smem_u32(&hbuf[0][bt_f][U0 + u_f]);
        haddr1 = smem_u32(&hbuf[1][bt_f][U0 + u_f]);
    }

    for (int i = tid; i < 2 * HH; i += 384) hbuf[0][i >> 8][i & 255] = 0.f;

    float mx = -3.0e38f;

    // initial full sync: h0 + smem ready across the cluster
    asm volatile("barrier.cluster.arrive.aligned;" ::: "memory");
    asm volatile("barrier.cluster.wait.aligned;"   ::: "memory");

    for (int st = 0; st < LL; st++) {
        const int p = st & 1;
        const int t = d ? (LL - 1 - st) : st;

        // gi prefetch (h-independent) issued BEFORE blocking on peers
        float gir = 0.f, giz = 0.f, gin = 0.f;
        if (tid < 128) {
            const long gb = ((long)bglob * LL + t) * GG + U0 + u_f;
            gir = __ldg(&gi[gb]);
            giz = __ldg(&gi[gb + HH]);
            gin = __ldg(&gi[gb + 2 * HH]);
        }

        // close previous round's barrier (peers' h for this step now visible)
        if (st > 0)
            asm volatile("barrier.cluster.wait.aligned;" ::: "memory");

        // dot products: h loads are warp-broadcast LDS, weights in registers
        float4 a0 = make_float4(0.f, 0.f, 0.f, 0.f);
        float4 a1 = make_float4(0.f, 0.f, 0.f, 0.f);
        {
            const float* h0 = &hbuf[p][0][half * 128];
            const float* h1 = &hbuf[p][1][half * 128];
            #pragma unroll
            for (int i = 0; i < 32; i++) {
                float4 wv = wreg[i];
                float4 x0 = *(const float4*)&h0[i * 4];
                float4 x1 = *(const float4*)&h1[i * 4];
                a0.x += wv.x * x0.x; a0.y += wv.y * x0.y;
                a0.z += wv.z * x0.z; a0.w += wv.w * x0.w;
                a1.x += wv.x * x1.x; a1.y += wv.y * x1.y;
                a1.z += wv.z * x1.z; a1.w += wv.w * x1.w;
            }
        }
        const float s0 = (a0.x + a0.y) + (a0.z + a0.w);
        const float s1 = (a1.x + a1.y) + (a1.z + a1.w);

        part[half][0][rw] = s0;
        part[half][1][rw] = s1;

        // producer/consumer split: only the 4 finalize warps block here
        if (tid >= 128) {
            asm volatile("bar.arrive 1, 384;" ::: "memory");
        } else {
            asm volatile("bar.sync 1, 384;" ::: "memory");

            const float gr = part[0][bt_f][u_f]       + part[1][bt_f][u_f];
            const float gz = part[0][bt_f][64 + u_f]  + part[1][bt_f][64 + u_f];
            const float gn = part[0][bt_f][128 + u_f] + part[1][bt_f][128 + u_f];
            const float hp = hbuf[p][bt_f][U0 + u_f];

            const float r  = __fdividef(1.f, 1.f + __expf(-(gir + gr + br)));
            const float z  = __fdividef(1.f, 1.f + __expf(-(giz + gz + bz)));
            const float ex = __expf(-2.f * (gin + r * (gn + bn)));
            const float nn = __fdividef(1.f - ex, 1.f + ex);   // tanh
            const float hn = (1.f - z) * nn + z * hp;
            mx = fmaxf(mx, hn);

            hbuf[p ^ 1][bt_f][U0 + u_f] = hn;
            if (st < LL - 1) {
                const uint32_t ha = (p ^ 1) ? haddr1 : haddr0;
                #pragma unroll
                for (uint32_t rk = 0; rk < 4; rk++) {
                    if (rk != cr) st_cluster_f32(ha, rk, hn);
                }
            }
        }

        // open this round's barrier (release of the remote h stores)
        if (st < LL - 1)
            asm volatile("barrier.cluster.arrive.aligned;" ::: "memory");
    }

    if (tid < 128) out[bglob * 512 + d * 256 + U0 + u_f] = mx;
}

// ---------------------------------------------------------------------------
// kernel_launch
// ---------------------------------------------------------------------------
extern "C" void kernel_launch(void* const* d_in, const int* in_sizes, int n_in,
                              void* d_out, int out_size)
{
    const int*   tokens = (const int*)  d_in[0];
    const float* emb    = (const float*)d_in[1];
    const float* Wc     = (const float*)d_in[2];
    const float* bc     = (const float*)d_in[3];
    const float* Wih_f  = (const float*)d_in[4];
    const float* Whh_f  = (const float*)d_in[5];
    const float* bih_f  = (const float*)d_in[6];
    const float* bhh_f  = (const float*)d_in[7];
    const float* Wih_b  = (const float*)d_in[8];
    const float* Whh_b  = (const float*)d_in[9];
    const float* bih_b  = (const float*)d_in[10];
    const float* bhh_b  = (const float*)d_in[11];
    float* out = (float*)d_out;

    const int SMV = KV_SMEM_FLOATS * 4;
    const int SMT = KT_SMEM_FLOATS * 4;
    const int SM2 = K2_SMEM_FLOATS * 4;

    cudaFuncSetAttribute(k_vocab, cudaFuncAttributeMaxDynamicSharedMemorySize, SMV);
    cudaFuncSetAttribute(k_tree,  cudaFuncAttributeMaxDynamicSharedMemorySize, SMT);
    cudaFuncSetAttribute(k_gi,    cudaFuncAttributeMaxDynamicSharedMemorySize, SM2);

    k_setup<<<208, 256>>>(Wc, Wih_f, Wih_b);
    k_vocab<<<(VV + 63) / 64, 256, SMV>>>(emb);
    k_tree<<<BB * LL / 2, 256, SMT>>>(tokens, bc);
    dim3 g2(64, 6, 2);
    k_gi<<<g2, 256, SM2>>>(bih_f, bih_b);
    k_gru<<<128, 384>>>(Whh_f, bhh_f, Whh_b, bhh_b, out);
}

// round 11
// speedup vs baseline: 1.0288x; 1.0288x over previous
#include <cuda_runtime.h>
#include <cuda_bf16.h>
#include <cstdint>

// Problem constants (fixed by the dataset)
#define BB 32      // batch
#define LL 128     // sequence length
#define TT 63      // tree nodes (2^6 - 1)
#define EE 128     // embedding dim
#define CC 128     // conv/encoder channels
#define HH 256     // GRU hidden
#define GG 768     // 3*H gate columns
#define VV 50000   // vocab

// ---------------------------------------------------------------------------
// f32x2 helpers
// ---------------------------------------------------------------------------
__device__ __forceinline__ unsigned long long fma2(unsigned long long a,
                                                   unsigned long long b,
                                                   unsigned long long c) {
    unsigned long long d;
    asm("fma.rn.f32x2 %0, %1, %2, %3;" : "=l"(d) : "l"(a), "l"(b), "l"(c));
    return d;
}
__device__ __forceinline__ unsigned long long pk2(float v) {
    unsigned long long r;
    asm("mov.b64 %0, {%1, %1};" : "=l"(r) : "f"(v));
    return r;
}
__device__ __forceinline__ float2 upk(unsigned long long v) {
    float2 f;
    asm("mov.b64 {%0, %1}, %2;" : "=f"(f.x), "=f"(f.y) : "l"(v));
    return f;
}
__device__ __forceinline__ uint32_t smem_u32(const void* p) {
    uint32_t a;
    asm("{ .reg .u64 t; cvta.to.shared.u64 t, %1; cvt.u32.u64 %0, t; }"
        : "=r"(a) : "l"(p));
    return a;
}

// ---------------------------------------------------------------------------
// Device scratch (static only)
// ---------------------------------------------------------------------------
__device__ float d_WcT[EE * CC];            // [k][c]
__device__ float d_WihT0[CC * GG];          // [k][g]
__device__ float d_WihT1[CC * GG];
__device__ float d_P[(long)VV * CC];        // projected vocab: P[v][c]
__device__ float d_enc[BB * LL * CC];
__device__ float d_gi0[(long)BB * LL * GG];
__device__ float d_gi1[(long)BB * LL * GG];

// ---------------------------------------------------------------------------
// Setup: coalesced tiled transposes (32x33 smem tiles, both sides coalesced).
// Grid: 208 blocks = 96 (Wih_f) + 96 (Wih_b) + 16 (Wc). 256 threads.
// ---------------------------------------------------------------------------
__global__ void __launch_bounds__(256) k_setup(const float* __restrict__ Wc,
                                               const float* __restrict__ Wih_f,
                                               const float* __restrict__ Wih_b)
{
    __shared__ float t[32][33];
    const int bid = blockIdx.x;
    const int tid = threadIdx.x;
    const int r = tid >> 5;    // warp -> rows r, r+8, r+16, r+24
    const int j = tid & 31;

    if (bid < 192) {
        const int d = (bid >= 96) ? 1 : 0;
        const float* W  = d ? Wih_b : Wih_f;
        float*       WT = d ? d_WihT1 : d_WihT0;
        const int tb = bid - d * 96;
        const int g0 = (tb % 24) * 32;
        const int k0 = (tb / 24) * 32;
        #pragma unroll
        for (int rr = r; rr < 32; rr += 8)
            t[rr][j] = W[(g0 + rr) * CC + k0 + j];
        __syncthreads();
        #pragma unroll
        for (int rr = r; rr < 32; rr += 8)
            WT[(k0 + rr) * GG + g0 + j] = t[j][rr];
    } else {
        const int tb = bid - 192;          // 0..15
        const int c0 = (tb & 3) * 32;
        const int e0 = (tb >> 2) * 32;
        #pragma unroll
        for (int rr = r; rr < 32; rr += 8)
            t[rr][j] = Wc[(c0 + rr) * EE + e0 + j];
        __syncthreads();
        #pragma unroll
        for (int rr = r; rr < 32; rr += 8)
            d_WcT[(e0 + rr) * CC + c0 + j] = t[j][rr];
    }
}

// ---------------------------------------------------------------------------
// KV: projected-vocab table  P[v] = Wc @ emb[v]
// ---------------------------------------------------------------------------
#define KV_WS 0
#define KV_ES 16384
#define KV_SMEM_FLOATS 24576

__global__ void __launch_bounds__(256, 2) k_vocab(const float* __restrict__ emb)
{
    extern __shared__ float sm[];
    float* ws = sm + KV_WS;   // WcT [k][c] 128x128
    float* es = sm + KV_ES;   // emb rows [64][128]

    const int m0  = blockIdx.x * 64;
    const int tid = threadIdx.x;

    for (int idx = tid; idx < (128 * 128) / 4; idx += 256)
        ((float4*)ws)[idx] = ((const float4*)d_WcT)[idx];
    for (int idx = tid; idx < (64 * 128) / 4; idx += 256) {
        int i  = idx >> 5;
        int k4 = (idx & 31) << 2;
        float4 v = make_float4(0.f, 0.f, 0.f, 0.f);
        if (m0 + i < VV) v = *(const float4*)&emb[(long)(m0 + i) * EE + k4];
        *(float4*)&es[i * 128 + k4] = v;
    }
    __syncthreads();

    const int w     = tid >> 5;
    const int lane  = tid & 31;
    const int c4    = lane << 2;
    const int ibase = w * 8;

    unsigned long long acc2[8][2];
    #pragma unroll
    for (int n = 0; n < 8; n++) { acc2[n][0] = 0ull; acc2[n][1] = 0ull; }

    #pragma unroll 2
    for (int k = 0; k < EE; k += 4) {
        ulonglong2 wu[4];
        #pragma unroll
        for (int kk = 0; kk < 4; kk++)
            wu[kk] = *(const ulonglong2*)&ws[(k + kk) * 128 + c4];

        #pragma unroll
        for (int g = 0; g < 2; g++) {
            float4 e4[4];
            #pragma unroll
            for (int n = 0; n < 4; n++)
                e4[n] = *(float4*)&es[(ibase + g * 4 + n) * 128 + k];
            #pragma unroll
            for (int kk = 0; kk < 4; kk++) {
                #pragma unroll
                for (int n = 0; n < 4; n++) {
                    float ev = (kk == 0) ? e4[n].x : (kk == 1) ? e4[n].y
                             : (kk == 2) ? e4[n].z : e4[n].w;
                    unsigned long long eb = pk2(ev);
                    acc2[g * 4 + n][0] = fma2(eb, wu[kk].x, acc2[g * 4 + n][0]);
                    acc2[g * 4 + n][1] = fma2(eb, wu[kk].y, acc2[g * 4 + n][1]);
                }
            }
        }
    }

    #pragma unroll
    for (int n = 0; n < 8; n++) {
        const int row = m0 + ibase + n;
        if (row < VV) {
            float2 lo = upk(acc2[n][0]);
            float2 hi = upk(acc2[n][1]);
            float4 r = make_float4(lo.x, lo.y, hi.x, hi.y);
            *(float4*)&d_P[(long)row * CC + c4] = r;
        }
    }
}

// ---------------------------------------------------------------------------
// KT: tree encoder = gather P[tok] + bc, heap accumulate, max, relu.
// ---------------------------------------------------------------------------
#define KT_STG 0
#define KT_BCS 16384
#define KT_TKS 16512
#define KT_SMEM_FLOATS 16672

__global__ void __launch_bounds__(256) k_tree(const int* __restrict__ tokens,
                                              const float* __restrict__ bc)
{
    extern __shared__ float sm[];
    float* stg = sm + KT_STG;
    float* bcs = sm + KT_BCS;
    int*   tks = (int*)(sm + KT_TKS);

    const int bl0 = blockIdx.x * 2;
    const int tid = threadIdx.x;

    if (tid < 2 * TT) tks[tid] = tokens[bl0 * TT + tid];
    if (tid < CC)     bcs[tid] = bc[tid];
    __syncthreads();

    const float4* P4 = (const float4*)d_P;
    for (int ci = tid; ci < 126 * 32; ci += 256) {
        const int tl = ci >> 5;
        const int j  = ci & 31;
        const int g  = (tl >= TT) ? 1 : 0;
        const int t  = tl - g * TT;
        float4 v = __ldg(&P4[(long)tks[tl] * 32 + j]);
        float4 b = *(const float4*)&bcs[j * 4];
        v.x += b.x; v.y += b.y; v.z += b.z; v.w += b.w;
        *(float4*)&stg[(g * 64 + t) * 128 + j * 4] = v;
    }
    __syncthreads();

    {
        const int g = tid >> 7;
        const int c = tid & 127;
        float* S = stg + (g * 64) * 128 + c;
        float mx = -3.0e38f;
        #pragma unroll
        for (int t = TT - 1; t >= 31; t--) mx = fmaxf(mx, S[t * 128]);
        #pragma unroll
        for (int t = 30; t >= 0; t--) {
            float v = S[t * 128] + S[(2 * t + 1) * 128] + S[(2 * t + 2) * 128];
            S[t * 128] = v;
            mx = fmaxf(mx, v);
        }
        d_enc[(bl0 + g) * CC + c] = fmaxf(mx, 0.f);
    }
}

// ---------------------------------------------------------------------------
// K2: gi[d] = enc @ Wih[d]^T + bih[d]
// ---------------------------------------------------------------------------
#define K2_WS 0
#define K2_ES 16384
#define K2_BI 24576
#define K2_SMEM_FLOATS 24704

__global__ void __launch_bounds__(256, 2) k_gi(const float* __restrict__ bih_f,
                                               const float* __restrict__ bih_b)
{
    extern __shared__ float sm[];
    float* ws  = sm + K2_WS;
    float* es  = sm + K2_ES;
    float* bis = sm + K2_BI;

    const int mt = blockIdx.x;
    const int nt = blockIdx.y;
    const int d  = blockIdx.z;
    const int m0 = mt * 64;
    const int g0 = nt * 128;
    const int tid = threadIdx.x;

    const float* WT  = d ? d_WihT1 : d_WihT0;
    const float* bih = d ? bih_b   : bih_f;
    float*       gi  = d ? d_gi1   : d_gi0;

    for (int idx = tid; idx < (128 * 128) / 4; idx += 256) {
        int k  = idx >> 5;
        int j4 = (idx & 31) << 2;
        float4 v = *(const float4*)&WT[k * GG + g0 + j4];
        *(float4*)&ws[k * 128 + j4] = v;
    }
    for (int idx = tid; idx < (64 * 128) / 4; idx += 256) {
        int i  = idx >> 5;
        int k4 = (idx & 31) << 2;
        float4 v = *(const float4*)&d_enc[(m0 + i) * CC + k4];
        *(float4*)&es[i * 128 + k4] = v;
    }
    if (tid < 128) bis[tid] = bih[g0 + tid];
    __syncthreads();

    const int w     = tid >> 5;
    const int lane  = tid & 31;
    const int c4    = lane << 2;
    const int ibase = w * 8;

    unsigned long long acc2[8][2];
    #pragma unroll
    for (int n = 0; n < 8; n++) { acc2[n][0] = 0ull; acc2[n][1] = 0ull; }

    #pragma unroll 2
    for (int k = 0; k < CC; k += 4) {
        ulonglong2 wu[4];
        #pragma unroll
        for (int kk = 0; kk < 4; kk++)
            wu[kk] = *(const ulonglong2*)&ws[(k + kk) * 128 + c4];

        #pragma unroll
        for (int g = 0; g < 2; g++) {
            float4 e4[4];
            #pragma unroll
            for (int n = 0; n < 4; n++)
                e4[n] = *(float4*)&es[(ibase + g * 4 + n) * 128 + k];
            #pragma unroll
            for (int kk = 0; kk < 4; kk++) {
                #pragma unroll
                for (int n = 0; n < 4; n++) {
                    float ev = (kk == 0) ? e4[n].x : (kk == 1) ? e4[n].y
                             : (kk == 2) ? e4[n].z : e4[n].w;
                    unsigned long long eb = pk2(ev);
                    acc2[g * 4 + n][0] = fma2(eb, wu[kk].x, acc2[g * 4 + n][0]);
                    acc2[g * 4 + n][1] = fma2(eb, wu[kk].y, acc2[g * 4 + n][1]);
                }
            }
        }
    }

    float4 bv = *(float4*)&bis[c4];
    #pragma unroll
    for (int n = 0; n < 8; n++) {
        float2 lo = upk(acc2[n][0]);
        float2 hi = upk(acc2[n][1]);
        float4 r;
        r.x = lo.x + bv.x;
        r.y = lo.y + bv.y;
        r.z = hi.x + bv.z;
        r.w = hi.y + bv.w;
        *(float4*)&gi[(long)(m0 + ibase + n) * GG + g0 + c4] = r;
    }
}

// ---------------------------------------------------------------------------
// K3: cluster-local bidirectional GRU — exact R5 core (199.5us, proven twice).
// ---------------------------------------------------------------------------
__device__ __forceinline__ void st_cluster_f32(uint32_t local_addr, uint32_t rank, float v) {
    asm volatile(
        "{\n\t"
        ".reg .b32 r;\n\t"
        "mapa.shared::cluster.u32 r, %0, %1;\n\t"
        "st.shared::cluster.f32 [r], %2;\n\t"
        "}"
        :: "r"(local_addr), "r"(rank), "f"(v) : "memory");
}

__global__ void __launch_bounds__(384, 1) __cluster_dims__(4, 1, 1)
k_gru(const float* __restrict__ Whh_f, const float* __restrict__ bhh_f,
      const float* __restrict__ Whh_b, const float* __restrict__ bhh_b,
      float* __restrict__ out)
{
    __shared__ float hbuf[2][2][HH];     // [buf][bt][unit]
    __shared__ float part[2][2][192];    // [half][bt][row] partial dots

    const int tid = threadIdx.x;
    uint32_t cr;
    asm("mov.u32 %0, %%cluster_ctarank;" : "=r"(cr));

    const int cid = blockIdx.x >> 2;
    const int d   = cid >> 4;
    const int bp  = cid & 15;
    const int U0  = (int)cr << 6;

    const float* Whh = d ? Whh_b : Whh_f;
    const float* bhh = d ? bhh_b : bhh_f;
    const float* gi  = d ? d_gi1 : d_gi0;

    const int w    = tid >> 5;
    const int lane = tid & 31;
    const int rw   = (w % 6) * 32 + lane;  // 0..191  (gate*64 + u)
    const int half = w / 6;                // 0 or 1

    const int gate = rw >> 6, uu = rw & 63;
    float4 wreg[32];
    {
        const float* wrow = &Whh[(gate * HH + U0 + uu) * HH + half * 128];
        #pragma unroll
        for (int i = 0; i < 32; i++) wreg[i] = *(const float4*)&wrow[i * 4];
    }

    const int u_f   = tid & 63;
    const int bt_f  = tid >> 6;
    const int bglob = bp * 2 + bt_f;
    float br = 0.f, bz = 0.f, bn = 0.f;
    uint32_t haddr0 = 0, haddr1 = 0;
    if (tid < 128) {
        br = bhh[U0 + u_f];
        bz = bhh[HH + U0 + u_f];
        bn = bhh[2 * HH + U0 + u_f];
        haddr0 = smem_u32(&hbuf[0][bt_f][U0 + u_f]);
        haddr1 = smem_u32(&hbuf[1][bt_f][U0 + u_f]);
    }

    for (int i = tid; i < 2 * HH; i += 384) hbuf[0][i >> 8][i & 255] = 0.f;

    float mx = -3.0e38f;

    asm volatile("barrier.cluster.arrive.aligned;" ::: "memory");
    asm volatile("barrier.cluster.wait.aligned;"   ::: "memory");

    for (int st = 0; st < LL; st++) {
        const int p = st & 1;
        const int t = d ? (LL - 1 - st) : st;

        float gir = 0.f, giz = 0.f, gin = 0.f;
        if (tid < 128) {
            const long gb = ((long)bglob * LL + t) * GG + U0 + u_f;
            gir = __ldg(&gi[gb]);
            giz = __ldg(&gi[gb + HH]);
            gin = __ldg(&gi[gb + 2 * HH]);
        }

        float4 a0 = make_float4(0.f, 0.f, 0.f, 0.f);
        float4 a1 = make_float4(0.f, 0.f, 0.f, 0.f);
        {
            const float* h0 = &hbuf[p][0][half * 128];
            const float* h1 = &hbuf[p][1][half * 128];
            #pragma unroll
            for (int i = 0; i < 32; i++) {
                float4 wv = wreg[i];
                float4 x0 = *(const float4*)&h0[i * 4];
                float4 x1 = *(const float4*)&h1[i * 4];
                a0.x += wv.x * x0.x; a0.y += wv.y * x0.y;
                a0.z += wv.z * x0.z; a0.w += wv.w * x0.w;
                a1.x += wv.x * x1.x; a1.y += wv.y * x1.y;
                a1.z += wv.z * x1.z; a1.w += wv.w * x1.w;
            }
        }
        const float s0 = (a0.x + a0.y) + (a0.z + a0.w);
        const float s1 = (a1.x + a1.y) + (a1.z + a1.w);

        part[half][0][rw] = s0;
        part[half][1][rw] = s1;
        __syncthreads();

        if (tid < 128) {
            const float gr = part[0][bt_f][u_f]       + part[1][bt_f][u_f];
            const float gz = part[0][bt_f][64 + u_f]  + part[1][bt_f][64 + u_f];
            const float gn = part[0][bt_f][128 + u_f] + part[1][bt_f][128 + u_f];
            const float hp = hbuf[p][bt_f][U0 + u_f];

            const float r  = 1.f / (1.f + __expf(-(gir + gr + br)));
            const float z  = 1.f / (1.f + __expf(-(giz + gz + bz)));
            const float nn = tanhf(gin + r * (gn + bn));
            const float hn = (1.f - z) * nn + z * hp;
            mx = fmaxf(mx, hn);

            hbuf[p ^ 1][bt_f][U0 + u_f] = hn;
            const uint32_t ha = (p ^ 1) ? haddr1 : haddr0;
            #pragma unroll
            for (uint32_t rk = 0; rk < 4; rk++) {
                if (rk != cr) st_cluster_f32(ha, rk, hn);
            }
        }

        asm volatile("barrier.cluster.arrive.aligned;" ::: "memory");
        asm volatile("barrier.cluster.wait.aligned;"   ::: "memory");
    }

    if (tid < 128) out[bglob * 512 + d * 256 + U0 + u_f] = mx;
}

// ---------------------------------------------------------------------------
// kernel_launch
// ---------------------------------------------------------------------------
extern "C" void kernel_launch(void* const* d_in, const int* in_sizes, int n_in,
                              void* d_out, int out_size)
{
    const int*   tokens = (const int*)  d_in[0];
    const float* emb    = (const float*)d_in[1];
    const float* Wc     = (const float*)d_in[2];
    const float* bc     = (const float*)d_in[3];
    const float* Wih_f  = (const float*)d_in[4];
    const float* Whh_f  = (const float*)d_in[5];
    const float* bih_f  = (const float*)d_in[6];
    const float* bhh_f  = (const float*)d_in[7];
    const float* Wih_b  = (const float*)d_in[8];
    const float* Whh_b  = (const float*)d_in[9];
    const float* bih_b  = (const float*)d_in[10];
    const float* bhh_b  = (const float*)d_in[11];
    float* out = (float*)d_out;

    const int SMV = KV_SMEM_FLOATS * 4;
    const int SMT = KT_SMEM_FLOATS * 4;
    const int SM2 = K2_SMEM_FLOATS * 4;

    cudaFuncSetAttribute(k_vocab, cudaFuncAttributeMaxDynamicSharedMemorySize, SMV);
    cudaFuncSetAttribute(k_tree,  cudaFuncAttributeMaxDynamicSharedMemorySize, SMT);
    cudaFuncSetAttribute(k_gi,    cudaFuncAttributeMaxDynamicSharedMemorySize, SM2);

    k_setup<<<208, 256>>>(Wc, Wih_f, Wih_b);
    k_vocab<<<(VV + 63) / 64, 256, SMV>>>(emb);
    k_tree<<<BB * LL / 2, 256, SMT>>>(tokens, bc);
    dim3 g2(64, 6, 2);
    k_gi<<<g2, 256, SM2>>>(bih_f, bih_b);
    k_gru<<<128, 384>>>(Whh_f, bhh_f, Whh_b, bhh_b, out);
}

// round 13
// speedup vs baseline: 1.0357x; 1.0067x over previous
#include <cuda_runtime.h>
#include <cuda_bf16.h>
#include <cstdint>

// Problem constants (fixed by the dataset)
#define BB 32      // batch
#define LL 128     // sequence length
#define TT 63      // tree nodes (2^6 - 1)
#define EE 128     // embedding dim
#define CC 128     // conv/encoder channels
#define HH 256     // GRU hidden
#define GG 768     // 3*H gate columns
#define VV 50000   // vocab

// ---------------------------------------------------------------------------
// f32x2 helpers
// ---------------------------------------------------------------------------
__device__ __forceinline__ unsigned long long fma2(unsigned long long a,
                                                   unsigned long long b,
                                                   unsigned long long c) {
    unsigned long long d;
    asm("fma.rn.f32x2 %0, %1, %2, %3;" : "=l"(d) : "l"(a), "l"(b), "l"(c));
    return d;
}
__device__ __forceinline__ unsigned long long pk2(float v) {
    unsigned long long r;
    asm("mov.b64 %0, {%1, %1};" : "=l"(r) : "f"(v));
    return r;
}
__device__ __forceinline__ float2 upk(unsigned long long v) {
    float2 f;
    asm("mov.b64 {%0, %1}, %2;" : "=f"(f.x), "=f"(f.y) : "l"(v));
    return f;
}
__device__ __forceinline__ uint32_t smem_u32(const void* p) {
    uint32_t a;
    asm("{ .reg .u64 t; cvta.to.shared.u64 t, %1; cvt.u32.u64 %0, t; }"
        : "=r"(a) : "l"(p));
    return a;
}

// ---------------------------------------------------------------------------
// Device scratch (static only)
// ---------------------------------------------------------------------------
__device__ float d_WcT[EE * CC];            // [k][c]
__device__ float d_WihT0[CC * GG];          // [k][g]
__device__ float d_WihT1[CC * GG];
__device__ float d_P[(long)VV * CC];        // projected vocab: P[v][c]
__device__ float d_enc[BB * LL * CC];
__device__ float d_gi0[(long)BB * LL * GG];
__device__ float d_gi1[(long)BB * LL * GG];

// ---------------------------------------------------------------------------
// Setup: coalesced tiled transposes (32x33 smem tiles, both sides coalesced).
// ---------------------------------------------------------------------------
__global__ void __launch_bounds__(256) k_setup(const float* __restrict__ Wc,
                                               const float* __restrict__ Wih_f,
                                               const float* __restrict__ Wih_b)
{
    __shared__ float t[32][33];
    const int bid = blockIdx.x;
    const int tid = threadIdx.x;
    const int r = tid >> 5;
    const int j = tid & 31;

    if (bid < 192) {
        const int d = (bid >= 96) ? 1 : 0;
        const float* W  = d ? Wih_b : Wih_f;
        float*       WT = d ? d_WihT1 : d_WihT0;
        const int tb = bid - d * 96;
        const int g0 = (tb % 24) * 32;
        const int k0 = (tb / 24) * 32;
        #pragma unroll
        for (int rr = r; rr < 32; rr += 8)
            t[rr][j] = W[(g0 + rr) * CC + k0 + j];
        __syncthreads();
        #pragma unroll
        for (int rr = r; rr < 32; rr += 8)
            WT[(k0 + rr) * GG + g0 + j] = t[j][rr];
    } else {
        const int tb = bid - 192;
        const int c0 = (tb & 3) * 32;
        const int e0 = (tb >> 2) * 32;
        #pragma unroll
        for (int rr = r; rr < 32; rr += 8)
            t[rr][j] = Wc[(c0 + rr) * EE + e0 + j];
        __syncthreads();
        #pragma unroll
        for (int rr = r; rr < 32; rr += 8)
            d_WcT[(e0 + rr) * CC + c0 + j] = t[j][rr];
    }
}

// ---------------------------------------------------------------------------
// KV: projected-vocab table  P[v] = Wc @ emb[v]
// ---------------------------------------------------------------------------
#define KV_WS 0
#define KV_ES 16384
#define KV_SMEM_FLOATS 24576

__global__ void __launch_bounds__(256, 2) k_vocab(const float* __restrict__ emb)
{
    extern __shared__ float sm[];
    float* ws = sm + KV_WS;
    float* es = sm + KV_ES;

    const int m0  = blockIdx.x * 64;
    const int tid = threadIdx.x;

    for (int idx = tid; idx < (128 * 128) / 4; idx += 256)
        ((float4*)ws)[idx] = ((const float4*)d_WcT)[idx];
    for (int idx = tid; idx < (64 * 128) / 4; idx += 256) {
        int i  = idx >> 5;
        int k4 = (idx & 31) << 2;
        float4 v = make_float4(0.f, 0.f, 0.f, 0.f);
        if (m0 + i < VV) v = *(const float4*)&emb[(long)(m0 + i) * EE + k4];
        *(float4*)&es[i * 128 + k4] = v;
    }
    __syncthreads();

    const int w     = tid >> 5;
    const int lane  = tid & 31;
    const int c4    = lane << 2;
    const int ibase = w * 8;

    unsigned long long acc2[8][2];
    #pragma unroll
    for (int n = 0; n < 8; n++) { acc2[n][0] = 0ull; acc2[n][1] = 0ull; }

    #pragma unroll 2
    for (int k = 0; k < EE; k += 4) {
        ulonglong2 wu[4];
        #pragma unroll
        for (int kk = 0; kk < 4; kk++)
            wu[kk] = *(const ulonglong2*)&ws[(k + kk) * 128 + c4];

        #pragma unroll
        for (int g = 0; g < 2; g++) {
            float4 e4[4];
            #pragma unroll
            for (int n = 0; n < 4; n++)
                e4[n] = *(float4*)&es[(ibase + g * 4 + n) * 128 + k];
            #pragma unroll
            for (int kk = 0; kk < 4; kk++) {
                #pragma unroll
                for (int n = 0; n < 4; n++) {
                    float ev = (kk == 0) ? e4[n].x : (kk == 1) ? e4[n].y
                             : (kk == 2) ? e4[n].z : e4[n].w;
                    unsigned long long eb = pk2(ev);
                    acc2[g * 4 + n][0] = fma2(eb, wu[kk].x, acc2[g * 4 + n][0]);
                    acc2[g * 4 + n][1] = fma2(eb, wu[kk].y, acc2[g * 4 + n][1]);
                }
            }
        }
    }

    #pragma unroll
    for (int n = 0; n < 8; n++) {
        const int row = m0 + ibase + n;
        if (row < VV) {
            float2 lo = upk(acc2[n][0]);
            float2 hi = upk(acc2[n][1]);
            float4 r = make_float4(lo.x, lo.y, hi.x, hi.y);
            *(float4*)&d_P[(long)row * CC + c4] = r;
        }
    }
}

// ---------------------------------------------------------------------------
// KT: tree encoder = gather P[tok] + bc, heap accumulate, max, relu.
// ---------------------------------------------------------------------------
#define KT_STG 0
#define KT_BCS 16384
#define KT_TKS 16512
#define KT_SMEM_FLOATS 16672

__global__ void __launch_bounds__(256) k_tree(const int* __restrict__ tokens,
                                              const float* __restrict__ bc)
{
    extern __shared__ float sm[];
    float* stg = sm + KT_STG;
    float* bcs = sm + KT_BCS;
    int*   tks = (int*)(sm + KT_TKS);

    const int bl0 = blockIdx.x * 2;
    const int tid = threadIdx.x;

    if (tid < 2 * TT) tks[tid] = tokens[bl0 * TT + tid];
    if (tid < CC)     bcs[tid] = bc[tid];
    __syncthreads();

    const float4* P4 = (const float4*)d_P;
    for (int ci = tid; ci < 126 * 32; ci += 256) {
        const int tl = ci >> 5;
        const int j  = ci & 31;
        const int g  = (tl >= TT) ? 1 : 0;
        const int t  = tl - g * TT;
        float4 v = __ldg(&P4[(long)tks[tl] * 32 + j]);
        float4 b = *(const float4*)&bcs[j * 4];
        v.x += b.x; v.y += b.y; v.z += b.z; v.w += b.w;
        *(float4*)&stg[(g * 64 + t) * 128 + j * 4] = v;
    }
    __syncthreads();

    {
        const int g = tid >> 7;
        const int c = tid & 127;
        float* S = stg + (g * 64) * 128 + c;
        float mx = -3.0e38f;
        #pragma unroll
        for (int t = TT - 1; t >= 31; t--) mx = fmaxf(mx, S[t * 128]);
        #pragma unroll
        for (int t = 30; t >= 0; t--) {
            float v = S[t * 128] + S[(2 * t + 1) * 128] + S[(2 * t + 2) * 128];
            S[t * 128] = v;
            mx = fmaxf(mx, v);
        }
        d_enc[(bl0 + g) * CC + c] = fmaxf(mx, 0.f);
    }
}

// ---------------------------------------------------------------------------
// K2: gi[d] = enc @ Wih[d]^T + bih[d] (+ bhh[d] for r/z gates ONLY — the
// n-gate bhh is r-modulated and must stay in the recurrent finalize)
// ---------------------------------------------------------------------------
#define K2_WS 0
#define K2_ES 16384
#define K2_BI 24576
#define K2_SMEM_FLOATS 24704

__global__ void __launch_bounds__(256, 2) k_gi(const float* __restrict__ bih_f,
                                               const float* __restrict__ bih_b,
                                               const float* __restrict__ bhh_f,
                                               const float* __restrict__ bhh_b)
{
    extern __shared__ float sm[];
    float* ws  = sm + K2_WS;
    float* es  = sm + K2_ES;
    float* bis = sm + K2_BI;

    const int mt = blockIdx.x;
    const int nt = blockIdx.y;
    const int d  = blockIdx.z;
    const int m0 = mt * 64;
    const int g0 = nt * 128;
    const int tid = threadIdx.x;

    const float* WT  = d ? d_WihT1 : d_WihT0;
    const float* bih = d ? bih_b   : bih_f;
    const float* bhh = d ? bhh_b   : bhh_f;
    float*       gi  = d ? d_gi1   : d_gi0;

    for (int idx = tid; idx < (128 * 128) / 4; idx += 256) {
        int k  = idx >> 5;
        int j4 = (idx & 31) << 2;
        float4 v = *(const float4*)&WT[k * GG + g0 + j4];
        *(float4*)&ws[k * 128 + j4] = v;
    }
    for (int idx = tid; idx < (64 * 128) / 4; idx += 256) {
        int i  = idx >> 5;
        int k4 = (idx & 31) << 2;
        float4 v = *(const float4*)&d_enc[(m0 + i) * CC + k4];
        *(float4*)&es[i * 128 + k4] = v;
    }
    if (tid < 128) {
        // fold bhh only into r/z gate columns (g < 2*HH = 512)
        const int gc = g0 + tid;
        float b = bih[gc];
        if (gc < 2 * HH) b += bhh[gc];
        bis[tid] = b;
    }
    __syncthreads();

    const int w     = tid >> 5;
    const int lane  = tid & 31;
    const int c4    = lane << 2;
    const int ibase = w * 8;

    unsigned long long acc2[8][2];
    #pragma unroll
    for (int n = 0; n < 8; n++) { acc2[n][0] = 0ull; acc2[n][1] = 0ull; }

    #pragma unroll 2
    for (int k = 0; k < CC; k += 4) {
        ulonglong2 wu[4];
        #pragma unroll
        for (int kk = 0; kk < 4; kk++)
            wu[kk] = *(const ulonglong2*)&ws[(k + kk) * 128 + c4];

        #pragma unroll
        for (int g = 0; g < 2; g++) {
            float4 e4[4];
            #pragma unroll
            for (int n = 0; n < 4; n++)
                e4[n] = *(float4*)&es[(ibase + g * 4 + n) * 128 + k];
            #pragma unroll
            for (int kk = 0; kk < 4; kk++) {
                #pragma unroll
                for (int n = 0; n < 4; n++) {
                    float ev = (kk == 0) ? e4[n].x : (kk == 1) ? e4[n].y
                             : (kk == 2) ? e4[n].z : e4[n].w;
                    unsigned long long eb = pk2(ev);
                    acc2[g * 4 + n][0] = fma2(eb, wu[kk].x, acc2[g * 4 + n][0]);
                    acc2[g * 4 + n][1] = fma2(eb, wu[kk].y, acc2[g * 4 + n][1]);
                }
            }
        }
    }

    float4 bv = *(float4*)&bis[c4];
    #pragma unroll
    for (int n = 0; n < 8; n++) {
        float2 lo = upk(acc2[n][0]);
        float2 hi = upk(acc2[n][1]);
        float4 r;
        r.x = lo.x + bv.x;
        r.y = lo.y + bv.y;
        r.z = hi.x + bv.z;
        r.w = hi.y + bv.w;
        *(float4*)&gi[(long)(m0 + ibase + n) * GG + g0 + c4] = r;
    }
}

// ---------------------------------------------------------------------------
// K3: cluster-local bidirectional GRU — R5 core structure (proven).
// r/z biases pre-folded into gi; n-gate bhh kept as per-thread register bn
// (loaded once). Activations via __expf/__fdividef (err ~1e-6).
// ---------------------------------------------------------------------------
__device__ __forceinline__ void st_cluster_f32(uint32_t local_addr, uint32_t rank, float v) {
    asm volatile(
        "{\n\t"
        ".reg .b32 r;\n\t"
        "mapa.shared::cluster.u32 r, %0, %1;\n\t"
        "st.shared::cluster.f32 [r], %2;\n\t"
        "}"
        :: "r"(local_addr), "r"(rank), "f"(v) : "memory");
}

__global__ void __launch_bounds__(384, 1) __cluster_dims__(4, 1, 1)
k_gru(const float* __restrict__ Whh_f, const float* __restrict__ bhh_f,
      const float* __restrict__ Whh_b, const float* __restrict__ bhh_b,
      float* __restrict__ out)
{
    __shared__ float hbuf[2][2][HH];     // [buf][bt][unit]
    __shared__ float part[2][2][192];    // [half][bt][row] partial dots

    const int tid = threadIdx.x;
    uint32_t cr;
    asm("mov.u32 %0, %%cluster_ctarank;" : "=r"(cr));

    const int cid = blockIdx.x >> 2;
    const int d   = cid >> 4;
    const int bp  = cid & 15;
    const int U0  = (int)cr << 6;

    const float* Whh = d ? Whh_b : Whh_f;
    const float* bhh = d ? bhh_b : bhh_f;
    const float* gi  = d ? d_gi1 : d_gi0;

    const int w    = tid >> 5;
    const int lane = tid & 31;
    const int rw   = (w % 6) * 32 + lane;  // 0..191  (gate*64 + u)
    const int half = w / 6;                // 0 or 1

    const int gate = rw >> 6, uu = rw & 63;
    float4 wreg[32];
    {
        const float* wrow = &Whh[(gate * HH + U0 + uu) * HH + half * 128];
        #pragma unroll
        for (int i = 0; i < 32; i++) wreg[i] = *(const float4*)&wrow[i * 4];
    }

    const int u_f   = tid & 63;
    const int bt_f  = tid >> 6;
    const int bglob = bp * 2 + bt_f;
    float bn = 0.f;                        // n-gate recurrent bias (r-modulated)
    uint32_t haddr0 = 0, haddr1 = 0;
    if (tid < 128) {
        bn = bhh[2 * HH + U0 + u_f];
        haddr0 = smem_u32(&hbuf[0][bt_f][U0 + u_f]);
        haddr1 = smem_u32(&hbuf[1][bt_f][U0 + u_f]);
    }

    for (int i = tid; i < 2 * HH; i += 384) hbuf[0][i >> 8][i & 255] = 0.f;

    float mx = -3.0e38f;

    asm volatile("barrier.cluster.arrive.aligned;" ::: "memory");
    asm volatile("barrier.cluster.wait.aligned;"   ::: "memory");

    for (int st = 0; st < LL; st++) {
        const int p = st & 1;
        const int t = d ? (LL - 1 - st) : st;

        float gir = 0.f, giz = 0.f, gin = 0.f;
        if (tid < 128) {
            const long gb = ((long)bglob * LL + t) * GG + U0 + u_f;
            gir = __ldg(&gi[gb]);
            giz = __ldg(&gi[gb + HH]);
            gin = __ldg(&gi[gb + 2 * HH]);
        }

        float4 a0 = make_float4(0.f, 0.f, 0.f, 0.f);
        float4 a1 = make_float4(0.f, 0.f, 0.f, 0.f);
        {
            const float* h0 = &hbuf[p][0][half * 128];
            const float* h1 = &hbuf[p][1][half * 128];
            #pragma unroll
            for (int i = 0; i < 32; i++) {
                float4 wv = wreg[i];
                float4 x0 = *(const float4*)&h0[i * 4];
                float4 x1 = *(const float4*)&h1[i * 4];
                a0.x += wv.x * x0.x; a0.y += wv.y * x0.y;
                a0.z += wv.z * x0.z; a0.w += wv.w * x0.w;
                a1.x += wv.x * x1.x; a1.y += wv.y * x1.y;
                a1.z += wv.z * x1.z; a1.w += wv.w * x1.w;
            }
        }
        const float s0 = (a0.x + a0.y) + (a0.z + a0.w);
        const float s1 = (a1.x + a1.y) + (a1.z + a1.w);

        part[half][0][rw] = s0;
        part[half][1][rw] = s1;
        __syncthreads();

        if (tid < 128) {
            const float gr = part[0][bt_f][u_f]       + part[1][bt_f][u_f];
            const float gz = part[0][bt_f][64 + u_f]  + part[1][bt_f][64 + u_f];
            const float gn = part[0][bt_f][128 + u_f] + part[1][bt_f][128 + u_f];
            const float hp = hbuf[p][bt_f][U0 + u_f];

            // r/z biases pre-folded into gi; n-gate: gin + r*(gn + bn)
            const float r  = __fdividef(1.f, 1.f + __expf(-(gir + gr)));
            const float z  = __fdividef(1.f, 1.f + __expf(-(giz + gz)));
            const float ex = __expf(-2.f * (gin + r * (gn + bn)));
            const float nn = __fdividef(1.f - ex, 1.f + ex);   // tanh
            const float hn = (1.f - z) * nn + z * hp;
            mx = fmaxf(mx, hn);

            hbuf[p ^ 1][bt_f][U0 + u_f] = hn;
            const uint32_t ha = (p ^ 1) ? haddr1 : haddr0;
            #pragma unroll
            for (uint32_t rk = 0; rk < 4; rk++) {
                if (rk != cr) st_cluster_f32(ha, rk, hn);
            }
        }

        asm volatile("barrier.cluster.arrive.aligned;" ::: "memory");
        asm volatile("barrier.cluster.wait.aligned;"   ::: "memory");
    }

    if (tid < 128) out[bglob * 512 + d * 256 + U0 + u_f] = mx;
}

// ---------------------------------------------------------------------------
// kernel_launch
// ---------------------------------------------------------------------------
extern "C" void kernel_launch(void* const* d_in, const int* in_sizes, int n_in,
                              void* d_out, int out_size)
{
    const int*   tokens = (const int*)  d_in[0];
    const float* emb    = (const float*)d_in[1];
    const float* Wc     = (const float*)d_in[2];
    const float* bc     = (const float*)d_in[3];
    const float* Wih_f  = (const float*)d_in[4];
    const float* Whh_f  = (const float*)d_in[5];
    const float* bih_f  = (const float*)d_in[6];
    const float* bhh_f  = (const float*)d_in[7];
    const float* Wih_b  = (const float*)d_in[8];
    const float* Whh_b  = (const float*)d_in[9];
    const float* bih_b  = (const float*)d_in[10];
    const float* bhh_b  = (const float*)d_in[11];
    float* out = (float*)d_out;

    const int SMV = KV_SMEM_FLOATS * 4;
    const int SMT = KT_SMEM_FLOATS * 4;
    const int SM2 = K2_SMEM_FLOATS * 4;

    cudaFuncSetAttribute(k_vocab, cudaFuncAttributeMaxDynamicSharedMemorySize, SMV);
    cudaFuncSetAttribute(k_tree,  cudaFuncAttributeMaxDynamicSharedMemorySize, SMT);
    cudaFuncSetAttribute(k_gi,    cudaFuncAttributeMaxDynamicSharedMemorySize, SM2);

    k_setup<<<208, 256>>>(Wc, Wih_f, Wih_b);
    k_vocab<<<(VV + 63) / 64, 256, SMV>>>(emb);
    k_tree<<<BB * LL / 2, 256, SMT>>>(tokens, bc);
    dim3 g2(64, 6, 2);
    k_gi<<<g2, 256, SM2>>>(bih_f, bih_b, bhh_f, bhh_b);
    k_gru<<<128, 384>>>(Whh_f, bhh_f, Whh_b, bhh_b, out);
}